// round 1
// baseline (speedup 1.0000x reference)
#include <cuda_runtime.h>
#include <cuda_fp16.h>
#include <cstdint>
#include <cstddef>

// ---------------- scratch (device globals; no allocs allowed) ----------------
#define BDIM 64
#define SDIM 64
#define DDIM 2048
#define HHE  8
#define HD   256
#define INTER 16384
#define ROWS (BDIM*SDIM)            // 4096

__device__ float g_h1[ROWS*DDIM];      // rmsnorm output (reused for both norms)
__device__ float g_q [ROWS*DDIM];
__device__ float g_k [ROWS*HD];
__device__ float g_v [ROWS*HD];
__device__ float g_ao[ROWS*DDIM];      // attention output (B,S,H*HD)
__device__ float g_gate[(size_t)ROWS*INTER];
__device__ float g_up  [(size_t)ROWS*INTER];

// ---------------- helpers ----------------
__device__ __forceinline__ uint32_t f2tf(float x) {
    uint32_t r; asm("cvt.rna.tf32.f32 %0, %1;" : "=r"(r) : "f"(x)); return r;
}
__device__ __forceinline__ void mma_tf32(float* c, const uint32_t* a, const uint32_t* b) {
    asm volatile("mma.sync.aligned.m16n8k8.row.col.f32.tf32.tf32.f32 "
                 "{%0,%1,%2,%3}, {%4,%5,%6,%7}, {%8,%9}, {%0,%1,%2,%3};"
                 : "+f"(c[0]), "+f"(c[1]), "+f"(c[2]), "+f"(c[3])
                 : "r"(a[0]), "r"(a[1]), "r"(a[2]), "r"(a[3]), "r"(b[0]), "r"(b[1]));
}
__device__ __forceinline__ void cp16(void* dst, const void* src) {
    uint32_t d = (uint32_t)__cvta_generic_to_shared(dst);
    asm volatile("cp.async.cg.shared.global [%0], [%1], 16;" :: "r"(d), "l"(src));
}
#define CP_COMMIT() asm volatile("cp.async.commit_group;")

// ---------------- rmsnorm ----------------
__global__ __launch_bounds__(256) void rmsnorm_kernel(const float* __restrict__ x,
                                                      const float* __restrict__ w,
                                                      float* __restrict__ out) {
    int row = blockIdx.x;
    const float4* x4 = (const float4*)(x + (size_t)row * DDIM);
    const float4* w4 = (const float4*)w;
    float4* o4 = (float4*)(out + (size_t)row * DDIM);
    int t = threadIdx.x;
    float4 a = x4[t], b = x4[t + 256];
    float s = a.x*a.x + a.y*a.y + a.z*a.z + a.w*a.w
            + b.x*b.x + b.y*b.y + b.z*b.z + b.w*b.w;
    #pragma unroll
    for (int o = 16; o > 0; o >>= 1) s += __shfl_xor_sync(0xffffffffu, s, o);
    __shared__ float red[8];
    if ((t & 31) == 0) red[t >> 5] = s;
    __syncthreads();
    float tot = 0.f;
    #pragma unroll
    for (int i = 0; i < 8; i++) tot += red[i];
    float r = rsqrtf(tot * (1.0f / DDIM) + 1e-6f);
    float4 wa = w4[t], wb = w4[t + 256];
    float4 oa, ob;
    oa.x = a.x*r*(1.f+wa.x); oa.y = a.y*r*(1.f+wa.y); oa.z = a.z*r*(1.f+wa.z); oa.w = a.w*r*(1.f+wa.w);
    ob.x = b.x*r*(1.f+wb.x); ob.y = b.y*r*(1.f+wb.y); ob.z = b.z*r*(1.f+wb.z); ob.w = b.w*r*(1.f+wb.w);
    o4[t] = oa; o4[t + 256] = ob;
}

// ---------------- tf32 GEMM: C(M,N) = A(M,K) @ B(N,K)^T (+ optional residual) ----------------
__global__ __launch_bounds__(256) void gemm_tf32_kernel(
    const float* __restrict__ A, const float* __restrict__ B,
    float* __restrict__ C, const float* __restrict__ R,
    int M, int N, int K)
{
    __shared__ float As[2][128 * 20];
    __shared__ float Bs[2][128 * 20];
    const int tid = threadIdx.x;
    const int m0 = blockIdx.x * 128, n0 = blockIdx.y * 128;
    const int lane = tid & 31, warp = tid >> 5;
    const int wm = (warp & 1) * 64, wn = (warp >> 1) * 32;

    float acc[4][4][4];
    #pragma unroll
    for (int i = 0; i < 4; i++)
        #pragma unroll
        for (int j = 0; j < 4; j++)
            #pragma unroll
            for (int c = 0; c < 4; c++) acc[i][j][c] = 0.f;

    const int KT = K >> 4;
    // prologue: stage 0
    {
        #pragma unroll
        for (int i = 0; i < 2; i++) {
            int idx = tid + (i << 8);
            int m = idx >> 2, k4 = (idx & 3) << 2;
            cp16(&As[0][m * 20 + k4], A + (size_t)(m0 + m) * K + k4);
            cp16(&Bs[0][m * 20 + k4], B + (size_t)(n0 + m) * K + k4);
        }
        CP_COMMIT();
    }
    for (int kt = 0; kt < KT; ++kt) {
        int cur = kt & 1;
        if (kt + 1 < KT) {
            int koff = (kt + 1) << 4;
            int nxt = cur ^ 1;
            #pragma unroll
            for (int i = 0; i < 2; i++) {
                int idx = tid + (i << 8);
                int m = idx >> 2, k4 = (idx & 3) << 2;
                cp16(&As[nxt][m * 20 + k4], A + (size_t)(m0 + m) * K + koff + k4);
                cp16(&Bs[nxt][m * 20 + k4], B + (size_t)(n0 + m) * K + koff + k4);
            }
            CP_COMMIT();
            asm volatile("cp.async.wait_group 1;");
        } else {
            asm volatile("cp.async.wait_group 0;");
        }
        __syncthreads();
        const float* sA = As[cur];
        const float* sB = Bs[cur];
        #pragma unroll
        for (int kk = 0; kk < 16; kk += 8) {
            uint32_t af[4][4], bf[4][2];
            #pragma unroll
            for (int mi = 0; mi < 4; mi++) {
                int r = wm + mi * 16 + (lane >> 2);
                int c = kk + (lane & 3);
                af[mi][0] = f2tf(sA[r * 20 + c]);
                af[mi][1] = f2tf(sA[(r + 8) * 20 + c]);
                af[mi][2] = f2tf(sA[r * 20 + c + 4]);
                af[mi][3] = f2tf(sA[(r + 8) * 20 + c + 4]);
            }
            #pragma unroll
            for (int ni = 0; ni < 4; ni++) {
                int rr = wn + ni * 8 + (lane >> 2);
                int c = kk + (lane & 3);
                bf[ni][0] = f2tf(sB[rr * 20 + c]);
                bf[ni][1] = f2tf(sB[rr * 20 + c + 4]);
            }
            #pragma unroll
            for (int mi = 0; mi < 4; mi++)
                #pragma unroll
                for (int ni = 0; ni < 4; ni++)
                    mma_tf32(acc[mi][ni], af[mi], bf[ni]);
        }
        __syncthreads();
    }
    // epilogue
    #pragma unroll
    for (int mi = 0; mi < 4; mi++) {
        #pragma unroll
        for (int ni = 0; ni < 4; ni++) {
            int row = m0 + wm + mi * 16 + (lane >> 2);
            int col = n0 + wn + ni * 8 + ((lane & 3) << 1);
            size_t i0 = (size_t)row * N + col;
            size_t i1 = i0 + (size_t)8 * N;
            float* cc = acc[mi][ni];
            if (R) { cc[0] += R[i0]; cc[1] += R[i0 + 1]; cc[2] += R[i1]; cc[3] += R[i1 + 1]; }
            C[i0] = cc[0]; C[i0 + 1] = cc[1]; C[i1] = cc[2]; C[i1 + 1] = cc[3];
        }
    }
}

// ---------------- RoPE (faithful to the repo's B<->S transpose: angle uses pos_ids[s,b]) ----------------
__global__ void rope_kernel(float* __restrict__ t, const int* __restrict__ pos_ids,
                            const float* __restrict__ invf, int nh, int total) {
    int idx = blockIdx.x * blockDim.x + threadIdx.x;
    if (idx >= total) return;
    int d = idx & 127;
    int rest = idx >> 7;
    int h = rest % nh;
    int row = rest / nh;            // b*S + s
    int b = row >> 6, s = row & 63;
    float p = (float)pos_ids[s * SDIM + b];   // repo bug: index [s, b]
    float ang = p * invf[d];
    float c = cosf(ang), sn = sinf(ang);
    size_t base = ((size_t)row * nh + h) * HD;
    float x1 = t[base + d], x2 = t[base + d + 128];
    t[base + d]       = x1 * c - x2 * sn;
    t[base + d + 128] = x2 * c + x1 * sn;
}

// ---------------- attention: one block per (b,h) ----------------
// smem: Qs[64][260], Ks[256][66] (transposed), Vs[64][256], AS[64][68]
#define ATTN_SMEM ((64*260 + 256*66 + 64*256 + 64*68) * 4)
__global__ __launch_bounds__(256) void attn_kernel(
    const float* __restrict__ q, const float* __restrict__ k, const float* __restrict__ v,
    const float* __restrict__ mask, float* __restrict__ attn_out, float* __restrict__ ao)
{
    extern __shared__ float sm[];
    float* Qs = sm;                     // [64][260]
    float* Ks = Qs + 64 * 260;          // [256][66]  (d-major, transposed)
    float* Vs = Ks + 256 * 66;          // [64][256]
    float* AS = Vs + 64 * 256;          // [64][68]
    int h = blockIdx.x, b = blockIdx.y;
    int tid = threadIdx.x;
    const float* qb = q + ((size_t)b * SDIM * HHE + h) * HD;
    const float* kb = k + (size_t)b * SDIM * HD;
    const float* vb = v + (size_t)b * SDIM * HD;
    for (int i = tid; i < 64 * 256; i += 256) {
        int r = i >> 8, d = i & 255;
        Qs[r * 260 + d] = qb[(size_t)r * (HHE * HD) + d];
        Ks[d * 66 + r]  = kb[i];
        Vs[i]           = vb[i];
    }
    __syncthreads();

    int qi = tid >> 2, part = tid & 3;
    float sc[16];
    #pragma unroll
    for (int j = 0; j < 16; j++) sc[j] = 0.f;
    const float* qrow = Qs + qi * 260;
    #pragma unroll 4
    for (int d = 0; d < 256; d++) {
        float qd = qrow[d];
        const float* kd = Ks + d * 66 + part;
        #pragma unroll
        for (int j = 0; j < 16; j++) sc[j] += qd * kd[4 * j];
    }
    // f16-emulated softmax (matches scores.astype(f16) -> softmax -> astype(f32))
    const float* mrow = mask + ((size_t)b * 64 + qi) * 64;
    float sf[16];
    float mx = -INFINITY;
    #pragma unroll
    for (int j = 0; j < 16; j++) {
        int kj = part + 4 * j;
        float s = sc[j] * 0.0625f + mrow[kj];
        sf[j] = __half2float(__float2half(s));       // -1e9 -> -inf in f16
        mx = fmaxf(mx, sf[j]);
    }
    mx = fmaxf(mx, __shfl_xor_sync(0xffffffffu, mx, 1));
    mx = fmaxf(mx, __shfl_xor_sync(0xffffffffu, mx, 2));
    float sum = 0.f;
    #pragma unroll
    for (int j = 0; j < 16; j++) {
        float dd = __half2float(__float2half(sf[j] - mx));
        float e  = __half2float(__float2half(expf(dd)));
        sf[j] = e; sum += e;
    }
    sum += __shfl_xor_sync(0xffffffffu, sum, 1);
    sum += __shfl_xor_sync(0xffffffffu, sum, 2);
    float* asr = AS + qi * 68;
    float* aout = attn_out ? attn_out + (((size_t)b * HHE + h) * 64 + qi) * 64 : nullptr;
    float inv = 1.0f / sum;
    #pragma unroll
    for (int j = 0; j < 16; j++) {
        int kj = part + 4 * j;
        float a = __half2float(__float2half(sf[j] * inv * sum == sum ? sf[j] / sum : sf[j] / sum));
        a = __half2float(__float2half(sf[j] / sum));
        asr[kj] = a;
        if (aout) aout[kj] = a;
    }
    __syncthreads();

    float acc[64];
    #pragma unroll
    for (int d2 = 0; d2 < 64; d2++) acc[d2] = 0.f;
    for (int kj = 0; kj < 64; kj++) {
        float av = asr[kj];
        const float* vr = Vs + kj * 256 + part;
        #pragma unroll
        for (int d2 = 0; d2 < 64; d2++) acc[d2] += av * vr[4 * d2];
    }
    float* aorow = ao + (((size_t)b * 64 + qi) * HHE + h) * HD + part;
    #pragma unroll
    for (int d2 = 0; d2 < 64; d2++) aorow[4 * d2] = acc[d2];
}

// ---------------- gelu(gate) * up, in place into gate ----------------
__global__ void gelumul_kernel(float* __restrict__ gate, const float* __restrict__ up) {
    size_t i = (size_t)blockIdx.x * blockDim.x + threadIdx.x;
    float x = gate[i];
    float t = tanhf(0.7978845608028654f * (x + 0.044715f * x * x * x));
    gate[i] = 0.5f * x * (1.0f + t) * up[i];
}

// ---------------- launch ----------------
extern "C" void kernel_launch(void* const* d_in, const int* in_sizes, int n_in,
                              void* d_out, int out_size) {
    const float* x      = (const float*)d_in[0];
    const float* mask   = (const float*)d_in[1];
    const int*   pos    = (const int*)  d_in[2];
    const float* invf   = (const float*)d_in[3];
    const float* wq     = (const float*)d_in[4];
    const float* wk     = (const float*)d_in[5];
    const float* wv     = (const float*)d_in[6];
    const float* wo     = (const float*)d_in[7];
    const float* wgate  = (const float*)d_in[8];
    const float* wup    = (const float*)d_in[9];
    const float* wdown  = (const float*)d_in[10];
    const float* ln1    = (const float*)d_in[11];
    const float* ln2    = (const float*)d_in[12];

    float* out = (float*)d_out;
    float* out_h = out;                               // hidden_states (B,S,D)
    const int HID_N = ROWS * DDIM;                    // 8388608
    const int ATT_N = BDIM * HHE * SDIM * SDIM;       // 2097152
    float* out_attn = (out_size >= HID_N + ATT_N) ? out + HID_N : nullptr;

    float *h1, *q, *k, *v, *ao, *gate, *up;
    cudaGetSymbolAddress((void**)&h1,  g_h1);
    cudaGetSymbolAddress((void**)&q,   g_q);
    cudaGetSymbolAddress((void**)&k,   g_k);
    cudaGetSymbolAddress((void**)&v,   g_v);
    cudaGetSymbolAddress((void**)&ao,  g_ao);
    cudaGetSymbolAddress((void**)&gate,g_gate);
    cudaGetSymbolAddress((void**)&up,  g_up);

    cudaFuncSetAttribute(attn_kernel, cudaFuncAttributeMaxDynamicSharedMemorySize, ATTN_SMEM);

    // 1. rmsnorm 1
    rmsnorm_kernel<<<ROWS, 256>>>(x, ln1, h1);
    // 2. Q/K/V projections (tf32)
    gemm_tf32_kernel<<<dim3(ROWS/128, DDIM/128), 256>>>(h1, wq, q, nullptr, ROWS, DDIM, DDIM);
    gemm_tf32_kernel<<<dim3(ROWS/128, HD/128),   256>>>(h1, wk, k, nullptr, ROWS, HD,   DDIM);
    gemm_tf32_kernel<<<dim3(ROWS/128, HD/128),   256>>>(h1, wv, v, nullptr, ROWS, HD,   DDIM);
    // 3. RoPE
    {
        int totq = ROWS * HHE * 128;
        rope_kernel<<<totq / 256, 256>>>(q, pos, invf, HHE, totq);
        int totk = ROWS * 1 * 128;
        rope_kernel<<<totk / 256, 256>>>(k, pos, invf, 1, totk);
    }
    // 4. attention (writes attn output + context)
    attn_kernel<<<dim3(HHE, BDIM), 256, ATTN_SMEM>>>(q, k, v, mask, out_attn, ao);
    // 5. O projection + residual  -> hidden1 (in d_out)
    gemm_tf32_kernel<<<dim3(ROWS/128, DDIM/128), 256>>>(ao, wo, out_h, x, ROWS, DDIM, DDIM);
    // 6. rmsnorm 2
    rmsnorm_kernel<<<ROWS, 256>>>(out_h, ln2, h1);
    // 7. gate / up
    gemm_tf32_kernel<<<dim3(ROWS/128, INTER/128), 256>>>(h1, wgate, gate, nullptr, ROWS, INTER, DDIM);
    gemm_tf32_kernel<<<dim3(ROWS/128, INTER/128), 256>>>(h1, wup,   up,   nullptr, ROWS, INTER, DDIM);
    // 8. gelu(gate)*up
    gelumul_kernel<<<(unsigned)(((size_t)ROWS * INTER) / 256), 256>>>(gate, up);
    // 9. down projection + residual -> final hidden (in d_out)
    gemm_tf32_kernel<<<dim3(ROWS/128, DDIM/128), 256>>>(gate, wdown, out_h, out_h, ROWS, DDIM, INTER);
}

// round 2
// speedup vs baseline: 1.0161x; 1.0161x over previous
#include <cuda_runtime.h>
#include <cuda_fp16.h>
#include <cstdint>
#include <cstddef>

// ---------------- problem dims ----------------
#define BDIM 64
#define SDIM 64
#define DDIM 2048
#define HHE  8
#define HD   256
#define INTER 16384
#define ROWS (BDIM*SDIM)            // 4096

// ---------------- scratch (device globals; no allocs allowed) ----------------
__device__ float g_h1[ROWS*DDIM];      // rmsnorm output (tf32-rounded)
__device__ float g_q [ROWS*DDIM];
__device__ float g_k [ROWS*HD];
__device__ float g_v [ROWS*HD];
__device__ float g_ao[ROWS*DDIM];      // attention output (tf32-rounded)
__device__ float g_gate[(size_t)ROWS*INTER];
__device__ float g_up  [(size_t)ROWS*INTER];

// ---------------- helpers ----------------
__device__ __forceinline__ uint32_t f2tf(float x) {
    uint32_t r; asm("cvt.rna.tf32.f32 %0, %1;" : "=r"(r) : "f"(x)); return r;
}
__device__ __forceinline__ float round_tf32(float x) {
    return __uint_as_float(f2tf(x));
}
__device__ __forceinline__ void mma_tf32(float* c, const uint32_t* a, const uint32_t* b) {
    asm volatile("mma.sync.aligned.m16n8k8.row.col.f32.tf32.tf32.f32 "
                 "{%0,%1,%2,%3}, {%4,%5,%6,%7}, {%8,%9}, {%0,%1,%2,%3};"
                 : "+f"(c[0]), "+f"(c[1]), "+f"(c[2]), "+f"(c[3])
                 : "r"(a[0]), "r"(a[1]), "r"(a[2]), "r"(a[3]), "r"(b[0]), "r"(b[1]));
}
__device__ __forceinline__ void cp16(void* dst, const void* src) {
    uint32_t d = (uint32_t)__cvta_generic_to_shared(dst);
    asm volatile("cp.async.cg.shared.global [%0], [%1], 16;" :: "r"(d), "l"(src));
}
#define CP_COMMIT() asm volatile("cp.async.commit_group;")

// ---------------- rmsnorm (output rounded to tf32 for GEMM consumption) ----------------
__global__ __launch_bounds__(256) void rmsnorm_kernel(const float* __restrict__ x,
                                                      const float* __restrict__ w,
                                                      float* __restrict__ out) {
    int row = blockIdx.x;
    const float4* x4 = (const float4*)(x + (size_t)row * DDIM);
    const float4* w4 = (const float4*)w;
    float4* o4 = (float4*)(out + (size_t)row * DDIM);
    int t = threadIdx.x;
    float4 a = x4[t], b = x4[t + 256];
    float s = a.x*a.x + a.y*a.y + a.z*a.z + a.w*a.w
            + b.x*b.x + b.y*b.y + b.z*b.z + b.w*b.w;
    #pragma unroll
    for (int o = 16; o > 0; o >>= 1) s += __shfl_xor_sync(0xffffffffu, s, o);
    __shared__ float red[8];
    if ((t & 31) == 0) red[t >> 5] = s;
    __syncthreads();
    float tot = 0.f;
    #pragma unroll
    for (int i = 0; i < 8; i++) tot += red[i];
    float r = rsqrtf(tot * (1.0f / DDIM) + 1e-6f);
    float4 wa = w4[t], wb = w4[t + 256];
    float4 oa, ob;
    oa.x = round_tf32(a.x*r*(1.f+wa.x)); oa.y = round_tf32(a.y*r*(1.f+wa.y));
    oa.z = round_tf32(a.z*r*(1.f+wa.z)); oa.w = round_tf32(a.w*r*(1.f+wa.w));
    ob.x = round_tf32(b.x*r*(1.f+wb.x)); ob.y = round_tf32(b.y*r*(1.f+wb.y));
    ob.z = round_tf32(b.z*r*(1.f+wb.z)); ob.w = round_tf32(b.w*r*(1.f+wb.w));
    o4[t] = oa; o4[t + 256] = ob;
}

// ---------------- tf32 GEMM: C(M,N) = A(M,K) @ B(N,K)^T (+ optional residual) ----------------
// 128x128 CTA tile, 128 threads (4 warps, 64x64 each), BK=16, 4-stage cp.async.
// A must be pre-rounded to tf32 (producers do this). B converted in-loop.
#define GSTRIDE 20                       // pad: conflict-free fragment loads
#define GSTAGE  (2 * 128 * GSTRIDE)      // floats per stage (A then B)
#define GEMM_SMEM (4 * GSTAGE * 4)       // bytes (4 stages)

__device__ __forceinline__ void gemm_load_stage(
    const float* __restrict__ A, const float* __restrict__ B,
    float* __restrict__ stage, int m0, int n0, int K, int koff, int tid)
{
    float* sA = stage;
    float* sB = stage + 128 * GSTRIDE;
    #pragma unroll
    for (int i = 0; i < 4; i++) {
        int c = tid + (i << 7);                 // 0..511
        int row = c >> 2, k4 = (c & 3) << 2;
        cp16(&sA[row * GSTRIDE + k4], A + (size_t)(m0 + row) * K + koff + k4);
        cp16(&sB[row * GSTRIDE + k4], B + (size_t)(n0 + row) * K + koff + k4);
    }
    CP_COMMIT();
}

__global__ __launch_bounds__(128, 2) void gemm_tf32_kernel(
    const float* __restrict__ A, const float* __restrict__ B,
    float* __restrict__ C, const float* __restrict__ R,
    int M, int N, int K)
{
    extern __shared__ float smem[];
    const int tid  = threadIdx.x;
    const int lane = tid & 31, warp = tid >> 5;
    const int m0 = blockIdx.x * 128, n0 = blockIdx.y * 128;
    const int wm = (warp & 1) * 64, wn = (warp >> 1) * 64;

    float acc[4][8][4];
    #pragma unroll
    for (int i = 0; i < 4; i++)
        #pragma unroll
        for (int j = 0; j < 8; j++)
            #pragma unroll
            for (int c = 0; c < 4; c++) acc[i][j][c] = 0.f;

    const int KT = K >> 4;
    // prologue: stages 0..2
    gemm_load_stage(A, B, smem + 0 * GSTAGE, m0, n0, K,  0, tid);
    gemm_load_stage(A, B, smem + 1 * GSTAGE, m0, n0, K, 16, tid);
    gemm_load_stage(A, B, smem + 2 * GSTAGE, m0, n0, K, 32, tid);

    for (int kt = 0; kt < KT; ++kt) {
        asm volatile("cp.async.wait_group 2;");
        __syncthreads();
        if (kt + 3 < KT)
            gemm_load_stage(A, B, smem + ((kt + 3) & 3) * GSTAGE, m0, n0, K, (kt + 3) << 4, tid);
        else
            CP_COMMIT();   // keep group count aligned

        const float* sA = smem + (kt & 3) * GSTAGE;
        const float* sB = sA + 128 * GSTRIDE;
        #pragma unroll
        for (int kk = 0; kk < 16; kk += 8) {
            const int c = kk + (lane & 3);
            uint32_t af[4][4];
            #pragma unroll
            for (int mi = 0; mi < 4; mi++) {
                int r = wm + mi * 16 + (lane >> 2);
                af[mi][0] = __float_as_uint(sA[r * GSTRIDE + c]);
                af[mi][1] = __float_as_uint(sA[(r + 8) * GSTRIDE + c]);
                af[mi][2] = __float_as_uint(sA[r * GSTRIDE + c + 4]);
                af[mi][3] = __float_as_uint(sA[(r + 8) * GSTRIDE + c + 4]);
            }
            uint32_t bf[8][2];
            #pragma unroll
            for (int ni = 0; ni < 8; ni++) {
                int rr = wn + ni * 8 + (lane >> 2);
                bf[ni][0] = f2tf(sB[rr * GSTRIDE + c]);
                bf[ni][1] = f2tf(sB[rr * GSTRIDE + c + 4]);
            }
            #pragma unroll
            for (int mi = 0; mi < 4; mi++)
                #pragma unroll
                for (int ni = 0; ni < 8; ni++)
                    mma_tf32(acc[mi][ni], af[mi], bf[ni]);
        }
    }
    // epilogue
    #pragma unroll
    for (int mi = 0; mi < 4; mi++) {
        #pragma unroll
        for (int ni = 0; ni < 8; ni++) {
            int row = m0 + wm + mi * 16 + (lane >> 2);
            int col = n0 + wn + ni * 8 + ((lane & 3) << 1);
            size_t i0 = (size_t)row * N + col;
            size_t i1 = i0 + (size_t)8 * N;
            float* cc = acc[mi][ni];
            float2 v0 = make_float2(cc[0], cc[1]);
            float2 v1 = make_float2(cc[2], cc[3]);
            if (R) {
                float2 r0 = *(const float2*)(R + i0);
                float2 r1 = *(const float2*)(R + i1);
                v0.x += r0.x; v0.y += r0.y; v1.x += r1.x; v1.y += r1.y;
            }
            *(float2*)(C + i0) = v0;
            *(float2*)(C + i1) = v1;
        }
    }
}

// ---------------- RoPE (faithful to the repo's B<->S transpose: angle uses pos_ids[s,b]) ----------------
__global__ void rope_kernel(float* __restrict__ t, const int* __restrict__ pos_ids,
                            const float* __restrict__ invf, int nh, int total) {
    int idx = blockIdx.x * blockDim.x + threadIdx.x;
    if (idx >= total) return;
    int d = idx & 127;
    int rest = idx >> 7;
    int h = rest % nh;
    int row = rest / nh;            // b*S + s
    int b = row >> 6, s = row & 63;
    float p = (float)pos_ids[s * SDIM + b];   // repo bug: index [s, b]
    float ang = p * invf[d];
    float c = cosf(ang), sn = sinf(ang);
    size_t base = ((size_t)row * nh + h) * HD;
    float x1 = t[base + d], x2 = t[base + d + 128];
    t[base + d]       = x1 * c - x2 * sn;
    t[base + d + 128] = x2 * c + x1 * sn;
}

// ---------------- attention: one block per (b,h) ----------------
// smem: Qs[64][260], Ks[256][66] (transposed), Vs[64][256], AS[64][68]
#define ATTN_SMEM ((64*260 + 256*66 + 64*256 + 64*68) * 4)
__global__ __launch_bounds__(256) void attn_kernel(
    const float* __restrict__ q, const float* __restrict__ k, const float* __restrict__ v,
    const float* __restrict__ mask, float* __restrict__ attn_out, float* __restrict__ ao)
{
    extern __shared__ float sm[];
    float* Qs = sm;                     // [64][260]
    float* Ks = Qs + 64 * 260;          // [256][66]  (d-major, transposed)
    float* Vs = Ks + 256 * 66;          // [64][256]
    float* AS = Vs + 64 * 256;          // [64][68]
    int h = blockIdx.x, b = blockIdx.y;
    int tid = threadIdx.x;
    const float* qb = q + ((size_t)b * SDIM * HHE + h) * HD;
    const float* kb = k + (size_t)b * SDIM * HD;
    const float* vb = v + (size_t)b * SDIM * HD;
    for (int i = tid; i < 64 * 256; i += 256) {
        int r = i >> 8, d = i & 255;
        Qs[r * 260 + d] = qb[(size_t)r * (HHE * HD) + d];
        Ks[d * 66 + r]  = kb[i];
        Vs[i]           = vb[i];
    }
    __syncthreads();

    int qi = tid >> 2, part = tid & 3;
    float sc[16];
    #pragma unroll
    for (int j = 0; j < 16; j++) sc[j] = 0.f;
    const float* qrow = Qs + qi * 260;
    #pragma unroll 4
    for (int d = 0; d < 256; d++) {
        float qd = qrow[d];
        const float* kd = Ks + d * 66 + part;
        #pragma unroll
        for (int j = 0; j < 16; j++) sc[j] += qd * kd[4 * j];
    }
    // f16-emulated softmax (matches scores.astype(f16) -> softmax -> astype(f32))
    const float* mrow = mask + ((size_t)b * 64 + qi) * 64;
    float sf[16];
    float mx = -INFINITY;
    #pragma unroll
    for (int j = 0; j < 16; j++) {
        int kj = part + 4 * j;
        float s = sc[j] * 0.0625f + mrow[kj];
        sf[j] = __half2float(__float2half(s));       // -1e9 -> -inf in f16
        mx = fmaxf(mx, sf[j]);
    }
    mx = fmaxf(mx, __shfl_xor_sync(0xffffffffu, mx, 1));
    mx = fmaxf(mx, __shfl_xor_sync(0xffffffffu, mx, 2));
    float sum = 0.f;
    #pragma unroll
    for (int j = 0; j < 16; j++) {
        float dd = __half2float(__float2half(sf[j] - mx));
        float e  = __half2float(__float2half(expf(dd)));
        sf[j] = e; sum += e;
    }
    sum += __shfl_xor_sync(0xffffffffu, sum, 1);
    sum += __shfl_xor_sync(0xffffffffu, sum, 2);
    float* asr = AS + qi * 68;
    float* aout = attn_out ? attn_out + (((size_t)b * HHE + h) * 64 + qi) * 64 : nullptr;
    #pragma unroll
    for (int j = 0; j < 16; j++) {
        int kj = part + 4 * j;
        float a = __half2float(__float2half(sf[j] / sum));
        asr[kj] = a;
        if (aout) aout[kj] = a;
    }
    __syncthreads();

    float acc[64];
    #pragma unroll
    for (int d2 = 0; d2 < 64; d2++) acc[d2] = 0.f;
    for (int kj = 0; kj < 64; kj++) {
        float av = asr[kj];
        const float* vr = Vs + kj * 256 + part;
        #pragma unroll
        for (int d2 = 0; d2 < 64; d2++) acc[d2] += av * vr[4 * d2];
    }
    // context output, rounded to tf32 (consumed by O-proj GEMM A-side)
    float* aorow = ao + (((size_t)b * 64 + qi) * HHE + h) * HD + part;
    #pragma unroll
    for (int d2 = 0; d2 < 64; d2++) aorow[4 * d2] = round_tf32(acc[d2]);
}

// ---------------- gelu(gate) * up, in place into gate (tf32-rounded for down-proj) ----------------
__global__ void gelumul_kernel(float* __restrict__ gate, const float* __restrict__ up) {
    size_t i = (size_t)blockIdx.x * blockDim.x + threadIdx.x;
    float x = gate[i];
    float t = tanhf(0.7978845608028654f * (x + 0.044715f * x * x * x));
    gate[i] = round_tf32(0.5f * x * (1.0f + t) * up[i]);
}

// ---------------- launch ----------------
extern "C" void kernel_launch(void* const* d_in, const int* in_sizes, int n_in,
                              void* d_out, int out_size) {
    const float* x      = (const float*)d_in[0];
    const float* mask   = (const float*)d_in[1];
    const int*   pos    = (const int*)  d_in[2];
    const float* invf   = (const float*)d_in[3];
    const float* wq     = (const float*)d_in[4];
    const float* wk     = (const float*)d_in[5];
    const float* wv     = (const float*)d_in[6];
    const float* wo     = (const float*)d_in[7];
    const float* wgate  = (const float*)d_in[8];
    const float* wup    = (const float*)d_in[9];
    const float* wdown  = (const float*)d_in[10];
    const float* ln1    = (const float*)d_in[11];
    const float* ln2    = (const float*)d_in[12];

    float* out = (float*)d_out;
    float* out_h = out;                               // hidden_states (B,S,D)
    const int HID_N = ROWS * DDIM;                    // 8388608
    const int ATT_N = BDIM * HHE * SDIM * SDIM;       // 2097152
    float* out_attn = (out_size >= HID_N + ATT_N) ? out + HID_N : nullptr;

    float *h1, *q, *k, *v, *ao, *gate, *up;
    cudaGetSymbolAddress((void**)&h1,  g_h1);
    cudaGetSymbolAddress((void**)&q,   g_q);
    cudaGetSymbolAddress((void**)&k,   g_k);
    cudaGetSymbolAddress((void**)&v,   g_v);
    cudaGetSymbolAddress((void**)&ao,  g_ao);
    cudaGetSymbolAddress((void**)&gate,g_gate);
    cudaGetSymbolAddress((void**)&up,  g_up);

    cudaFuncSetAttribute(attn_kernel, cudaFuncAttributeMaxDynamicSharedMemorySize, ATTN_SMEM);
    cudaFuncSetAttribute(gemm_tf32_kernel, cudaFuncAttributeMaxDynamicSharedMemorySize, GEMM_SMEM);

    // 1. rmsnorm 1 (tf32-rounded output)
    rmsnorm_kernel<<<ROWS, 256>>>(x, ln1, h1);
    // 2. Q/K/V projections (tf32)
    gemm_tf32_kernel<<<dim3(ROWS/128, DDIM/128), 128, GEMM_SMEM>>>(h1, wq, q, nullptr, ROWS, DDIM, DDIM);
    gemm_tf32_kernel<<<dim3(ROWS/128, HD/128),   128, GEMM_SMEM>>>(h1, wk, k, nullptr, ROWS, HD,   DDIM);
    gemm_tf32_kernel<<<dim3(ROWS/128, HD/128),   128, GEMM_SMEM>>>(h1, wv, v, nullptr, ROWS, HD,   DDIM);
    // 3. RoPE
    {
        int totq = ROWS * HHE * 128;
        rope_kernel<<<totq / 256, 256>>>(q, pos, invf, HHE, totq);
        int totk = ROWS * 1 * 128;
        rope_kernel<<<totk / 256, 256>>>(k, pos, invf, 1, totk);
    }
    // 4. attention (writes attn probabilities + tf32-rounded context)
    attn_kernel<<<dim3(HHE, BDIM), 256, ATTN_SMEM>>>(q, k, v, mask, out_attn, ao);
    // 5. O projection + residual  -> hidden1 (in d_out)
    gemm_tf32_kernel<<<dim3(ROWS/128, DDIM/128), 128, GEMM_SMEM>>>(ao, wo, out_h, x, ROWS, DDIM, DDIM);
    // 6. rmsnorm 2
    rmsnorm_kernel<<<ROWS, 256>>>(out_h, ln2, h1);
    // 7. gate / up
    gemm_tf32_kernel<<<dim3(ROWS/128, INTER/128), 128, GEMM_SMEM>>>(h1, wgate, gate, nullptr, ROWS, INTER, DDIM);
    gemm_tf32_kernel<<<dim3(ROWS/128, INTER/128), 128, GEMM_SMEM>>>(h1, wup,   up,   nullptr, ROWS, INTER, DDIM);
    // 8. gelu(gate)*up (tf32-rounded)
    gelumul_kernel<<<(unsigned)(((size_t)ROWS * INTER) / 256), 256>>>(gate, up);
    // 9. down projection + residual -> final hidden (in d_out)
    gemm_tf32_kernel<<<dim3(ROWS/128, DDIM/128), 128, GEMM_SMEM>>>(gate, wdown, out_h, out_h, ROWS, DDIM, INTER);
}

// round 5
// speedup vs baseline: 1.6526x; 1.6265x over previous
#include <cuda_runtime.h>
#include <cuda_fp16.h>
#include <cstdint>
#include <cstddef>

// ---------------- problem dims ----------------
#define BDIM 64
#define SDIM 64
#define DDIM 2048
#define HHE  8
#define HD   256
#define INTER 16384
#define ROWS (BDIM*SDIM)            // 4096

// ---------------- scratch (device globals; no allocs allowed) ----------------
__device__ __align__(256) float  g_q [ROWS*DDIM];
__device__ __align__(256) float  g_k [ROWS*HD];
__device__ __align__(256) float  g_v [ROWS*HD];
__device__ __align__(256) float  g_gate[(size_t)ROWS*INTER];
__device__ __align__(256) __half g_h1h [ROWS*DDIM];
__device__ __align__(256) __half g_aoh [ROWS*DDIM];
__device__ __align__(256) __half g_mlph[(size_t)ROWS*INTER];
// fp16 weight copies
__device__ __align__(256) __half g_wqh[DDIM*DDIM];
__device__ __align__(256) __half g_wkh[HD*DDIM];
__device__ __align__(256) __half g_wvh[HD*DDIM];
__device__ __align__(256) __half g_woh[DDIM*DDIM];
__device__ __align__(256) __half g_wgh[(size_t)INTER*DDIM];
__device__ __align__(256) __half g_wuh[(size_t)INTER*DDIM];
__device__ __align__(256) __half g_wdh[(size_t)DDIM*INTER];

// ---------------- helpers ----------------
__device__ __forceinline__ void cp16s(uint32_t saddr, const void* gsrc) {
    asm volatile("cp.async.cg.shared.global [%0], [%1], 16;" :: "r"(saddr), "l"(gsrc));
}
#define CP_COMMIT() asm volatile("cp.async.commit_group;")

__device__ __forceinline__ void ldsm4(uint32_t* r, uint32_t a) {
    asm volatile("ldmatrix.sync.aligned.m8n8.x4.shared.b16 {%0,%1,%2,%3}, [%4];"
                 : "=r"(r[0]), "=r"(r[1]), "=r"(r[2]), "=r"(r[3]) : "r"(a));
}
__device__ __forceinline__ void ldsm2(uint32_t* r, uint32_t a) {
    asm volatile("ldmatrix.sync.aligned.m8n8.x2.shared.b16 {%0,%1}, [%2];"
                 : "=r"(r[0]), "=r"(r[1]) : "r"(a));
}
__device__ __forceinline__ void hmma(float* c, const uint32_t* a, const uint32_t* b) {
    asm volatile("mma.sync.aligned.m16n8k16.row.col.f32.f16.f16.f32 "
                 "{%0,%1,%2,%3}, {%4,%5,%6,%7}, {%8,%9}, {%0,%1,%2,%3};"
                 : "+f"(c[0]), "+f"(c[1]), "+f"(c[2]), "+f"(c[3])
                 : "r"(a[0]), "r"(a[1]), "r"(a[2]), "r"(a[3]), "r"(b[0]), "r"(b[1]));
}
__device__ __forceinline__ float gelu_tanh(float x) {
    float t = tanhf(0.7978845608028654f * (x + 0.044715f * x * x * x));
    return 0.5f * x * (1.0f + t);
}

// ---------------- fp32 -> fp16 convert ----------------
__global__ void cvt_h_kernel(const float4* __restrict__ in, __half2* __restrict__ out, int n4) {
    int i = blockIdx.x * blockDim.x + threadIdx.x;
    if (i >= n4) return;
    float4 v = in[i];
    out[2*i]   = __floats2half2_rn(v.x, v.y);
    out[2*i+1] = __floats2half2_rn(v.z, v.w);
}

// ---------------- rmsnorm (fp16 output for GEMM consumption) ----------------
__global__ __launch_bounds__(256) void rmsnorm_kernel(const float* __restrict__ x,
                                                      const float* __restrict__ w,
                                                      __half2* __restrict__ out) {
    int row = blockIdx.x;
    const float4* x4 = (const float4*)(x + (size_t)row * DDIM);
    const float4* w4 = (const float4*)w;
    __half2* o2 = out + (size_t)row * (DDIM/2);
    int t = threadIdx.x;
    float4 a = x4[t], b = x4[t + 256];
    float s = a.x*a.x + a.y*a.y + a.z*a.z + a.w*a.w
            + b.x*b.x + b.y*b.y + b.z*b.z + b.w*b.w;
    #pragma unroll
    for (int o = 16; o > 0; o >>= 1) s += __shfl_xor_sync(0xffffffffu, s, o);
    __shared__ float red[8];
    if ((t & 31) == 0) red[t >> 5] = s;
    __syncthreads();
    float tot = 0.f;
    #pragma unroll
    for (int i = 0; i < 8; i++) tot += red[i];
    float r = rsqrtf(tot * (1.0f / DDIM) + 1e-6f);
    float4 wa = w4[t], wb = w4[t + 256];
    o2[2*t]          = __floats2half2_rn(a.x*r*(1.f+wa.x), a.y*r*(1.f+wa.y));
    o2[2*t+1]        = __floats2half2_rn(a.z*r*(1.f+wa.z), a.w*r*(1.f+wa.w));
    o2[512 + 2*t]    = __floats2half2_rn(b.x*r*(1.f+wb.x), b.y*r*(1.f+wb.y));
    o2[512 + 2*t+1]  = __floats2half2_rn(b.z*r*(1.f+wb.z), b.w*r*(1.f+wb.w));
}

// ---------------- fp16 tensor-core GEMM ----------------
// C(M,N) = A(M,K:half) @ B(N,K:half)^T
// mode 0: C = acc (fp32)
// mode 1: C = acc + R
// mode 2: OH = half(gelu(R) * acc)   (fused gelu-mul; R = gate fp32)
// blockIdx.z selects (B2,C2) as operands (for fused K/V projections).
#define BKT 64
#define NSTAGE 4
#define STAGE_B 32768
#define GEMM_SMEM (NSTAGE * STAGE_B)

__global__ __launch_bounds__(256, 1) void gemm_h(
    const __half* __restrict__ A, const __half* __restrict__ Bw,
    const __half* __restrict__ B2,
    float* __restrict__ C, float* __restrict__ C2,
    const float* __restrict__ R, __half* __restrict__ OH,
    int N, int K, int mode)
{
    extern __shared__ char smem[];
    const uint32_t sbase = (uint32_t)__cvta_generic_to_shared(smem);
    const int tid = threadIdx.x;
    const int lane = tid & 31, warp = tid >> 5;
    const int m0 = blockIdx.x * 128, n0 = blockIdx.y * 128;
    const __half* Bx = blockIdx.z ? B2 : Bw;
    float* Cx = blockIdx.z ? C2 : C;

    const int wm = (warp >> 2) * 64;     // 0 or 64
    const int wn = (warp & 3) * 32;      // 0,32,64,96

    const __half* Abase = A + (size_t)m0 * K;
    const __half* Bbase = Bx + (size_t)n0 * K;

    float acc[4][4][4];
    #pragma unroll
    for (int i = 0; i < 4; i++)
        #pragma unroll
        for (int j = 0; j < 4; j++) {
            acc[i][j][0] = 0.f; acc[i][j][1] = 0.f; acc[i][j][2] = 0.f; acc[i][j][3] = 0.f;
        }

    const int KT = K / BKT;

    // per-thread cp.async mapping: ids tid*4 .. tid*4+3 over 1024 chunks/operand
    const int id0 = tid * 4;

    // prologue: stages 0..2
    #pragma unroll
    for (int p = 0; p < 3; p++) {
        uint32_t st = sbase + p * STAGE_B;
        #pragma unroll
        for (int i = 0; i < 4; i++) {
            int id = id0 + i;
            int row = id >> 3, c = id & 7;
            uint32_t soff = row * 128 + (((uint32_t)c ^ (row & 7)) << 4);
            cp16s(st + soff,         Abase + (size_t)row * K + p * BKT + c * 8);
            cp16s(st + 16384 + soff, Bbase + (size_t)row * K + p * BKT + c * 8);
        }
        CP_COMMIT();
    }

    for (int kt = 0; kt < KT; kt++) {
        if (kt + 3 < KT) {
            uint32_t st = sbase + ((kt + 3) & 3) * STAGE_B;
            int koff = (kt + 3) * BKT;
            #pragma unroll
            for (int i = 0; i < 4; i++) {
                int id = id0 + i;
                int row = id >> 3, c = id & 7;
                uint32_t soff = row * 128 + (((uint32_t)c ^ (row & 7)) << 4);
                cp16s(st + soff,         Abase + (size_t)row * K + koff + c * 8);
                cp16s(st + 16384 + soff, Bbase + (size_t)row * K + koff + c * 8);
            }
        }
        CP_COMMIT();
        asm volatile("cp.async.wait_group 3;");
        __syncthreads();

        const uint32_t st = sbase + (kt & 3) * STAGE_B;
        const uint32_t swz = lane & 7;
        #pragma unroll
        for (int ks = 0; ks < 4; ks++) {
            uint32_t a[4][4], b[4][2];
            #pragma unroll
            for (int mi = 0; mi < 4; mi++) {
                int row = wm + mi * 16 + (lane & 15);
                uint32_t ch = ((uint32_t)(2 * ks + (lane >> 4))) ^ swz;
                ldsm4(a[mi], st + row * 128 + (ch << 4));
            }
            #pragma unroll
            for (int ni = 0; ni < 4; ni++) {
                int row = wn + ni * 8 + (lane & 7);
                uint32_t ch = ((uint32_t)(2 * ks + ((lane >> 3) & 1))) ^ swz;
                ldsm2(b[ni], st + 16384 + row * 128 + (ch << 4));
            }
            #pragma unroll
            for (int mi = 0; mi < 4; mi++)
                #pragma unroll
                for (int ni = 0; ni < 4; ni++)
                    hmma(acc[mi][ni], a[mi], b[ni]);
        }
        __syncthreads();
    }

    // epilogue
    #pragma unroll
    for (int mi = 0; mi < 4; mi++) {
        #pragma unroll
        for (int ni = 0; ni < 4; ni++) {
            int r0 = m0 + wm + mi * 16 + (lane >> 2);
            int col = n0 + wn + ni * 8 + ((lane & 3) << 1);
            size_t i0 = (size_t)r0 * N + col;
            size_t i1 = i0 + (size_t)8 * N;
            float* cc = acc[mi][ni];
            if (mode == 0) {
                *(float2*)(Cx + i0) = make_float2(cc[0], cc[1]);
                *(float2*)(Cx + i1) = make_float2(cc[2], cc[3]);
            } else if (mode == 1) {
                float2 r0v = *(const float2*)(R + i0);
                float2 r1v = *(const float2*)(R + i1);
                *(float2*)(Cx + i0) = make_float2(cc[0] + r0v.x, cc[1] + r0v.y);
                *(float2*)(Cx + i1) = make_float2(cc[2] + r1v.x, cc[3] + r1v.y);
            } else {
                float2 g0 = *(const float2*)(R + i0);
                float2 g1 = *(const float2*)(R + i1);
                *(__half2*)(OH + i0) = __floats2half2_rn(gelu_tanh(g0.x) * cc[0],
                                                         gelu_tanh(g0.y) * cc[1]);
                *(__half2*)(OH + i1) = __floats2half2_rn(gelu_tanh(g1.x) * cc[2],
                                                         gelu_tanh(g1.y) * cc[3]);
            }
        }
    }
}

// ---------------- RoPE (faithful to repo's B<->S transpose) ----------------
__global__ void rope_kernel(float* __restrict__ t, const int* __restrict__ pos_ids,
                            const float* __restrict__ invf, int nh, int total) {
    int idx = blockIdx.x * blockDim.x + threadIdx.x;
    if (idx >= total) return;
    int d = idx & 127;
    int rest = idx >> 7;
    int h = rest % nh;
    int row = rest / nh;
    int b = row >> 6, s = row & 63;
    float p = (float)pos_ids[s * SDIM + b];   // repo bug: index [s, b]
    float ang = p * invf[d];
    float c = cosf(ang), sn = sinf(ang);
    size_t base = ((size_t)row * nh + h) * HD;
    float x1 = t[base + d], x2 = t[base + d + 128];
    t[base + d]       = x1 * c - x2 * sn;
    t[base + d + 128] = x2 * c + x1 * sn;
}

// ---------------- attention: one block per (b,h) ----------------
#define ATTN_SMEM ((64*260 + 256*66 + 64*256 + 64*68) * 4)
__global__ __launch_bounds__(256) void attn_kernel(
    const float* __restrict__ q, const float* __restrict__ k, const float* __restrict__ v,
    const float* __restrict__ mask, float* __restrict__ attn_out, __half* __restrict__ ao)
{
    extern __shared__ float sm[];
    float* Qs = sm;                     // [64][260]
    float* Ks = Qs + 64 * 260;          // [256][66]
    float* Vs = Ks + 256 * 66;          // [64][256]
    float* AS = Vs + 64 * 256;          // [64][68]
    int h = blockIdx.x, b = blockIdx.y;
    int tid = threadIdx.x;
    const float* qb = q + ((size_t)b * SDIM * HHE + h) * HD;
    const float* kb = k + (size_t)b * SDIM * HD;
    const float* vb = v + (size_t)b * SDIM * HD;
    for (int i = tid; i < 64 * 256; i += 256) {
        int r = i >> 8, d = i & 255;
        Qs[r * 260 + d] = qb[(size_t)r * (HHE * HD) + d];
        Ks[d * 66 + r]  = kb[i];
        Vs[i]           = vb[i];
    }
    __syncthreads();

    int qi = tid >> 2, part = tid & 3;
    float sc[16];
    #pragma unroll
    for (int j = 0; j < 16; j++) sc[j] = 0.f;
    const float* qrow = Qs + qi * 260;
    #pragma unroll 4
    for (int d = 0; d < 256; d++) {
        float qd = qrow[d];
        const float* kd = Ks + d * 66 + part;
        #pragma unroll
        for (int j = 0; j < 16; j++) sc[j] += qd * kd[4 * j];
    }
    const float* mrow = mask + ((size_t)b * 64 + qi) * 64;
    float sf[16];
    float mx = -INFINITY;
    #pragma unroll
    for (int j = 0; j < 16; j++) {
        int kj = part + 4 * j;
        float s = sc[j] * 0.0625f + mrow[kj];
        sf[j] = __half2float(__float2half(s));       // -1e9 -> -inf in f16
        mx = fmaxf(mx, sf[j]);
    }
    mx = fmaxf(mx, __shfl_xor_sync(0xffffffffu, mx, 1));
    mx = fmaxf(mx, __shfl_xor_sync(0xffffffffu, mx, 2));
    float sum = 0.f;
    #pragma unroll
    for (int j = 0; j < 16; j++) {
        float dd = __half2float(__float2half(sf[j] - mx));
        float e  = __half2float(__float2half(expf(dd)));
        sf[j] = e; sum += e;
    }
    sum += __shfl_xor_sync(0xffffffffu, sum, 1);
    sum += __shfl_xor_sync(0xffffffffu, sum, 2);
    float* asr = AS + qi * 68;
    float* aout = attn_out ? attn_out + (((size_t)b * HHE + h) * 64 + qi) * 64 : nullptr;
    #pragma unroll
    for (int j = 0; j < 16; j++) {
        int kj = part + 4 * j;
        float a = __half2float(__float2half(sf[j] / sum));
        asr[kj] = a;
        if (aout) aout[kj] = a;
    }
    __syncthreads();

    float acc[64];
    #pragma unroll
    for (int d2 = 0; d2 < 64; d2++) acc[d2] = 0.f;
    for (int kj = 0; kj < 64; kj++) {
        float av = asr[kj];
        const float* vr = Vs + kj * 256 + part;
        #pragma unroll
        for (int d2 = 0; d2 < 64; d2++) acc[d2] += av * vr[4 * d2];
    }
    // fp16 context output (row-major (B,S,H*HD)) for the O-proj GEMM
    __half* aorow = ao + (((size_t)b * 64 + qi) * HHE + h) * HD + part;
    #pragma unroll
    for (int d2 = 0; d2 < 64; d2++) aorow[4 * d2] = __float2half_rn(acc[d2]);
}

// ---------------- launch ----------------
extern "C" void kernel_launch(void* const* d_in, const int* in_sizes, int n_in,
                              void* d_out, int out_size) {
    const float* x      = (const float*)d_in[0];
    const float* mask   = (const float*)d_in[1];
    const int*   pos    = (const int*)  d_in[2];
    const float* invf   = (const float*)d_in[3];
    const float* wq     = (const float*)d_in[4];
    const float* wk     = (const float*)d_in[5];
    const float* wv     = (const float*)d_in[6];
    const float* wo     = (const float*)d_in[7];
    const float* wgate  = (const float*)d_in[8];
    const float* wup    = (const float*)d_in[9];
    const float* wdown  = (const float*)d_in[10];
    const float* ln1    = (const float*)d_in[11];
    const float* ln2    = (const float*)d_in[12];

    float* out = (float*)d_out;
    float* out_h = out;
    const int HID_N = ROWS * DDIM;
    const int ATT_N = BDIM * HHE * SDIM * SDIM;
    float* out_attn = (out_size >= HID_N + ATT_N) ? out + HID_N : nullptr;

    float *q, *k, *v, *gate;
    __half *h1h, *aoh, *mlph, *wqh, *wkh, *wvh, *woh, *wgh, *wuh, *wdh;
    cudaGetSymbolAddress((void**)&q,    g_q);
    cudaGetSymbolAddress((void**)&k,    g_k);
    cudaGetSymbolAddress((void**)&v,    g_v);
    cudaGetSymbolAddress((void**)&gate, g_gate);
    cudaGetSymbolAddress((void**)&h1h,  g_h1h);
    cudaGetSymbolAddress((void**)&aoh,  g_aoh);
    cudaGetSymbolAddress((void**)&mlph, g_mlph);
    cudaGetSymbolAddress((void**)&wqh,  g_wqh);
    cudaGetSymbolAddress((void**)&wkh,  g_wkh);
    cudaGetSymbolAddress((void**)&wvh,  g_wvh);
    cudaGetSymbolAddress((void**)&woh,  g_woh);
    cudaGetSymbolAddress((void**)&wgh,  g_wgh);
    cudaGetSymbolAddress((void**)&wuh,  g_wuh);
    cudaGetSymbolAddress((void**)&wdh,  g_wdh);

    cudaFuncSetAttribute(attn_kernel, cudaFuncAttributeMaxDynamicSharedMemorySize, ATTN_SMEM);
    cudaFuncSetAttribute(gemm_h, cudaFuncAttributeMaxDynamicSharedMemorySize, GEMM_SMEM);

    // 0. convert weights to fp16
    {
        auto cv = [](const float* src, __half* dst, size_t n) {
            int n4 = (int)(n / 4);
            cvt_h_kernel<<<(n4 + 255) / 256, 256>>>((const float4*)src, (__half2*)dst, n4);
        };
        cv(wq,    wqh, (size_t)DDIM*DDIM);
        cv(wk,    wkh, (size_t)HD*DDIM);
        cv(wv,    wvh, (size_t)HD*DDIM);
        cv(wo,    woh, (size_t)DDIM*DDIM);
        cv(wgate, wgh, (size_t)INTER*DDIM);
        cv(wup,   wuh, (size_t)INTER*DDIM);
        cv(wdown, wdh, (size_t)DDIM*INTER);
    }
    // 1. rmsnorm 1 -> fp16
    rmsnorm_kernel<<<ROWS, 256>>>(x, ln1, (__half2*)h1h);
    // 2. Q projection; K+V fused via blockIdx.z
    gemm_h<<<dim3(ROWS/128, DDIM/128), 256, GEMM_SMEM>>>(h1h, wqh, nullptr, q, nullptr,
                                                         nullptr, nullptr, DDIM, DDIM, 0);
    gemm_h<<<dim3(ROWS/128, HD/128, 2), 256, GEMM_SMEM>>>(h1h, wkh, wvh, k, v,
                                                          nullptr, nullptr, HD, DDIM, 0);
    // 3. RoPE
    {
        int totq = ROWS * HHE * 128;
        rope_kernel<<<totq / 256, 256>>>(q, pos, invf, HHE, totq);
        int totk = ROWS * 1 * 128;
        rope_kernel<<<totk / 256, 256>>>(k, pos, invf, 1, totk);
    }
    // 4. attention (fp32 probs to out, fp16 context to aoh)
    attn_kernel<<<dim3(HHE, BDIM), 256, ATTN_SMEM>>>(q, k, v, mask, out_attn, aoh);
    // 5. O projection + residual -> out_h
    gemm_h<<<dim3(ROWS/128, DDIM/128), 256, GEMM_SMEM>>>(aoh, woh, nullptr, out_h, nullptr,
                                                         x, nullptr, DDIM, DDIM, 1);
    // 6. rmsnorm 2 -> fp16
    rmsnorm_kernel<<<ROWS, 256>>>(out_h, ln2, (__half2*)h1h);
    // 7. gate GEMM (fp32 out)
    gemm_h<<<dim3(ROWS/128, INTER/128), 256, GEMM_SMEM>>>(h1h, wgh, nullptr, gate, nullptr,
                                                          nullptr, nullptr, INTER, DDIM, 0);
    // 8. up GEMM with fused gelu(gate)*up -> fp16 mlph
    gemm_h<<<dim3(ROWS/128, INTER/128), 256, GEMM_SMEM>>>(h1h, wuh, nullptr, nullptr, nullptr,
                                                          gate, mlph, INTER, DDIM, 2);
    // 9. down projection + residual -> out_h
    gemm_h<<<dim3(ROWS/128, DDIM/128), 256, GEMM_SMEM>>>(mlph, wdh, nullptr, out_h, nullptr,
                                                         out_h, nullptr, DDIM, INTER, 1);
}

// round 7
// speedup vs baseline: 2.4579x; 1.4873x over previous
#include <cuda_runtime.h>
#include <cuda_fp16.h>
#include <cstdint>
#include <cstddef>

// ---------------- problem dims ----------------
#define BDIM 64
#define SDIM 64
#define DDIM 2048
#define HHE  8
#define HD   256
#define INTER 16384
#define ROWS (BDIM*SDIM)            // 4096

// ---------------- scratch (device globals; no allocs allowed) ----------------
__device__ __align__(256) float  g_q [ROWS*DDIM];
__device__ __align__(256) float  g_k [ROWS*HD];
__device__ __align__(256) float  g_v [ROWS*HD];
__device__ __align__(256) float  g_gate[(size_t)ROWS*INTER];
__device__ __align__(256) __half g_h1h [ROWS*DDIM];
__device__ __align__(256) __half g_aoh [ROWS*DDIM];
__device__ __align__(256) __half g_mlph[(size_t)ROWS*INTER];
// fp16 weight copies
__device__ __align__(256) __half g_wqh[DDIM*DDIM];
__device__ __align__(256) __half g_wkh[HD*DDIM];
__device__ __align__(256) __half g_wvh[HD*DDIM];
__device__ __align__(256) __half g_woh[DDIM*DDIM];
__device__ __align__(256) __half g_wgh[(size_t)INTER*DDIM];
__device__ __align__(256) __half g_wuh[(size_t)INTER*DDIM];
__device__ __align__(256) __half g_wdh[(size_t)DDIM*INTER];

struct __align__(16) half2x4 { __half2 a, b, c, d; };

// ---------------- helpers ----------------
__device__ __forceinline__ void cp16s(uint32_t saddr, const void* gsrc) {
    asm volatile("cp.async.cg.shared.global [%0], [%1], 16;" :: "r"(saddr), "l"(gsrc));
}
#define CP_COMMIT() asm volatile("cp.async.commit_group;")

__device__ __forceinline__ void ldsm4(uint32_t* r, uint32_t a) {
    asm volatile("ldmatrix.sync.aligned.m8n8.x4.shared.b16 {%0,%1,%2,%3}, [%4];"
                 : "=r"(r[0]), "=r"(r[1]), "=r"(r[2]), "=r"(r[3]) : "r"(a));
}
__device__ __forceinline__ void hmma(float* c, const uint32_t* a, const uint32_t* b) {
    asm volatile("mma.sync.aligned.m16n8k16.row.col.f32.f16.f16.f32 "
                 "{%0,%1,%2,%3}, {%4,%5,%6,%7}, {%8,%9}, {%0,%1,%2,%3};"
                 : "+f"(c[0]), "+f"(c[1]), "+f"(c[2]), "+f"(c[3])
                 : "r"(a[0]), "r"(a[1]), "r"(a[2]), "r"(a[3]), "r"(b[0]), "r"(b[1]));
}
__device__ __forceinline__ float gelu_tanh(float x) {
    float t = tanhf(0.7978845608028654f * (x + 0.044715f * x * x * x));
    return 0.5f * x * (1.0f + t);
}

// ---------------- fp32 -> fp16 convert (8 elems/thread) ----------------
__global__ void cvt_h_kernel(const float4* __restrict__ in, half2x4* __restrict__ out, int n8) {
    int i = blockIdx.x * blockDim.x + threadIdx.x;
    if (i >= n8) return;
    float4 v0 = in[2*i], v1 = in[2*i+1];
    half2x4 o;
    o.a = __floats2half2_rn(v0.x, v0.y);
    o.b = __floats2half2_rn(v0.z, v0.w);
    o.c = __floats2half2_rn(v1.x, v1.y);
    o.d = __floats2half2_rn(v1.z, v1.w);
    out[i] = o;
}

// ---------------- rmsnorm (fp16 output for GEMM consumption) ----------------
__global__ __launch_bounds__(256) void rmsnorm_kernel(const float* __restrict__ x,
                                                      const float* __restrict__ w,
                                                      __half2* __restrict__ out) {
    int row = blockIdx.x;
    const float4* x4 = (const float4*)(x + (size_t)row * DDIM);
    const float4* w4 = (const float4*)w;
    __half2* o2 = out + (size_t)row * (DDIM/2);
    int t = threadIdx.x;
    float4 a = x4[t], b = x4[t + 256];
    float s = a.x*a.x + a.y*a.y + a.z*a.z + a.w*a.w
            + b.x*b.x + b.y*b.y + b.z*b.z + b.w*b.w;
    #pragma unroll
    for (int o = 16; o > 0; o >>= 1) s += __shfl_xor_sync(0xffffffffu, s, o);
    __shared__ float red[8];
    if ((t & 31) == 0) red[t >> 5] = s;
    __syncthreads();
    float tot = 0.f;
    #pragma unroll
    for (int i = 0; i < 8; i++) tot += red[i];
    float r = rsqrtf(tot * (1.0f / DDIM) + 1e-6f);
    float4 wa = w4[t], wb = w4[t + 256];
    o2[2*t]          = __floats2half2_rn(a.x*r*(1.f+wa.x), a.y*r*(1.f+wa.y));
    o2[2*t+1]        = __floats2half2_rn(a.z*r*(1.f+wa.z), a.w*r*(1.f+wa.w));
    o2[512 + 2*t]    = __floats2half2_rn(b.x*r*(1.f+wb.x), b.y*r*(1.f+wb.y));
    o2[512 + 2*t+1]  = __floats2half2_rn(b.z*r*(1.f+wb.z), b.w*r*(1.f+wb.w));
}

// ---------------- fp16 tensor-core GEMM ----------------
// C(M,N) = A(M,K:half) @ B(N,K:half)^T
// CTA tile 128x256, 8 warps (64x64 each), BK=64, 4-stage cp.async.
// mode 0: C = acc (fp32)
// mode 1: C = acc + R
// mode 2: OH = half(gelu(R) * acc)
// blockIdx.z selects (B2,C2) operands (fused K/V projections).
#define BKT 64
#define NSTAGE 4
#define STAGE_B ((128 + 256) * BKT * 2)     // 49152
#define GEMM_SMEM (NSTAGE * STAGE_B)        // 196608

__global__ __launch_bounds__(256, 1) void gemm_h(
    const __half* __restrict__ A, const __half* __restrict__ Bw,
    const __half* __restrict__ B2,
    float* __restrict__ C, float* __restrict__ C2,
    const float* __restrict__ R, __half* __restrict__ OH,
    int N, int K, int mode)
{
    extern __shared__ char smem[];
    const uint32_t sbase = (uint32_t)__cvta_generic_to_shared(smem);
    const int tid = threadIdx.x;
    const int lane = tid & 31, warp = tid >> 5;
    const int m0 = blockIdx.x * 128, n0 = blockIdx.y * 256;
    const __half* Bx = blockIdx.z ? B2 : Bw;
    float* Cx = blockIdx.z ? C2 : C;

    const int wm = (warp & 1) * 64;      // 0 or 64
    const int wn = (warp >> 1) * 64;     // 0,64,128,192

    const __half* Abase = A + (size_t)m0 * K;
    const __half* Bbase = Bx + (size_t)n0 * K;

    float acc[4][8][4];
    #pragma unroll
    for (int i = 0; i < 4; i++)
        #pragma unroll
        for (int j = 0; j < 8; j++) {
            acc[i][j][0] = 0.f; acc[i][j][1] = 0.f; acc[i][j][2] = 0.f; acc[i][j][3] = 0.f;
        }

    const int KT = K / BKT;
    // cp.async: 3072 chunks of 16B per stage (A:1024, B:2048), 12 per thread
    // prologue: stages 0..2
    #pragma unroll
    for (int p = 0; p < 3; p++) {
        uint32_t st = sbase + p * STAGE_B;
        #pragma unroll
        for (int i = 0; i < 12; i++) {
            int id = tid + (i << 8);
            if (id < 1024) {
                int row = id >> 3, c = id & 7;
                uint32_t soff = row * 128 + (((uint32_t)c ^ (row & 7)) << 4);
                cp16s(st + soff, Abase + (size_t)row * K + p * BKT + c * 8);
            } else {
                int idb = id - 1024;
                int row = idb >> 3, c = idb & 7;
                uint32_t soff = row * 128 + (((uint32_t)c ^ (row & 7)) << 4);
                cp16s(st + 16384 + soff, Bbase + (size_t)row * K + p * BKT + c * 8);
            }
        }
        CP_COMMIT();
    }

    for (int kt = 0; kt < KT; kt++) {
        if (kt + 3 < KT) {
            uint32_t st = sbase + ((kt + 3) & 3) * STAGE_B;
            int koff = (kt + 3) * BKT;
            #pragma unroll
            for (int i = 0; i < 12; i++) {
                int id = tid + (i << 8);
                if (id < 1024) {
                    int row = id >> 3, c = id & 7;
                    uint32_t soff = row * 128 + (((uint32_t)c ^ (row & 7)) << 4);
                    cp16s(st + soff, Abase + (size_t)row * K + koff + c * 8);
                } else {
                    int idb = id - 1024;
                    int row = idb >> 3, c = idb & 7;
                    uint32_t soff = row * 128 + (((uint32_t)c ^ (row & 7)) << 4);
                    cp16s(st + 16384 + soff, Bbase + (size_t)row * K + koff + c * 8);
                }
            }
        }
        CP_COMMIT();
        asm volatile("cp.async.wait_group 3;");
        __syncthreads();

        const uint32_t st = sbase + (kt & 3) * STAGE_B;
        const uint32_t swz = lane & 7;
        #pragma unroll
        for (int ks = 0; ks < 4; ks++) {
            uint32_t a[4][4], b[8][2];
            #pragma unroll
            for (int mi = 0; mi < 4; mi++) {
                int row = wm + mi * 16 + (lane & 15);
                uint32_t ch = ((uint32_t)(2 * ks + (lane >> 4))) ^ swz;
                ldsm4(a[mi], st + row * 128 + (ch << 4));
            }
            #pragma unroll
            for (int ni = 0; ni < 8; ni += 2) {
                // x4 covers tiles (n,k0),(n,k8),(n+8,k0),(n+8,k8)
                int row = wn + ni * 8 + ((lane >> 4) << 3) + (lane & 7);
                uint32_t ch = ((uint32_t)(2 * ks + ((lane >> 3) & 1))) ^ swz;
                uint32_t r4[4];
                ldsm4(r4, st + 16384 + row * 128 + (ch << 4));
                b[ni][0] = r4[0]; b[ni][1] = r4[1];
                b[ni+1][0] = r4[2]; b[ni+1][1] = r4[3];
            }
            #pragma unroll
            for (int mi = 0; mi < 4; mi++)
                #pragma unroll
                for (int ni = 0; ni < 8; ni++)
                    hmma(acc[mi][ni], a[mi], b[ni]);
        }
        __syncthreads();
    }

    // epilogue
    #pragma unroll
    for (int mi = 0; mi < 4; mi++) {
        #pragma unroll
        for (int ni = 0; ni < 8; ni++) {
            int r0 = m0 + wm + mi * 16 + (lane >> 2);
            int col = n0 + wn + ni * 8 + ((lane & 3) << 1);
            size_t i0 = (size_t)r0 * N + col;
            size_t i1 = i0 + (size_t)8 * N;
            float* cc = acc[mi][ni];
            if (mode == 0) {
                *(float2*)(Cx + i0) = make_float2(cc[0], cc[1]);
                *(float2*)(Cx + i1) = make_float2(cc[2], cc[3]);
            } else if (mode == 1) {
                float2 r0v = *(const float2*)(R + i0);
                float2 r1v = *(const float2*)(R + i1);
                *(float2*)(Cx + i0) = make_float2(cc[0] + r0v.x, cc[1] + r0v.y);
                *(float2*)(Cx + i1) = make_float2(cc[2] + r1v.x, cc[3] + r1v.y);
            } else {
                float2 g0 = *(const float2*)(R + i0);
                float2 g1 = *(const float2*)(R + i1);
                *(__half2*)(OH + i0) = __floats2half2_rn(gelu_tanh(g0.x) * cc[0],
                                                         gelu_tanh(g0.y) * cc[1]);
                *(__half2*)(OH + i1) = __floats2half2_rn(gelu_tanh(g1.x) * cc[2],
                                                         gelu_tanh(g1.y) * cc[3]);
            }
        }
    }
}

// ---------------- RoPE (faithful to repo's B<->S transpose) ----------------
__global__ void rope_kernel(float* __restrict__ t, const int* __restrict__ pos_ids,
                            const float* __restrict__ invf, int nh, int total) {
    int idx = blockIdx.x * blockDim.x + threadIdx.x;
    if (idx >= total) return;
    int d = idx & 127;
    int rest = idx >> 7;
    int h = rest % nh;
    int row = rest / nh;
    int b = row >> 6, s = row & 63;
    float p = (float)pos_ids[s * SDIM + b];   // repo bug: index [s, b]
    float ang = p * invf[d];
    float c = cosf(ang), sn = sinf(ang);
    size_t base = ((size_t)row * nh + h) * HD;
    float x1 = t[base + d], x2 = t[base + d + 128];
    t[base + d]       = x1 * c - x2 * sn;
    t[base + d + 128] = x2 * c + x1 * sn;
}

// ---------------- attention: one block per (b,h) ----------------
#define ATTN_SMEM ((64*260 + 256*66 + 64*256 + 64*68) * 4)
__global__ __launch_bounds__(256) void attn_kernel(
    const float* __restrict__ q, const float* __restrict__ k, const float* __restrict__ v,
    const float* __restrict__ mask, float* __restrict__ attn_out, __half* __restrict__ ao)
{
    extern __shared__ float sm[];
    float* Qs = sm;                     // [64][260]
    float* Ks = Qs + 64 * 260;          // [256][66]
    float* Vs = Ks + 256 * 66;          // [64][256]
    float* AS = Vs + 64 * 256;          // [64][68]
    int h = blockIdx.x, b = blockIdx.y;
    int tid = threadIdx.x;
    const float* qb = q + ((size_t)b * SDIM * HHE + h) * HD;
    const float* kb = k + (size_t)b * SDIM * HD;
    const float* vb = v + (size_t)b * SDIM * HD;
    for (int i = tid; i < 64 * 256; i += 256) {
        int r = i >> 8, d = i & 255;
        Qs[r * 260 + d] = qb[(size_t)r * (HHE * HD) + d];
        Ks[d * 66 + r]  = kb[i];
        Vs[i]           = vb[i];
    }
    __syncthreads();

    int qi = tid >> 2, part = tid & 3;
    float sc[16];
    #pragma unroll
    for (int j = 0; j < 16; j++) sc[j] = 0.f;
    const float* qrow = Qs + qi * 260;
    #pragma unroll 4
    for (int d = 0; d < 256; d++) {
        float qd = qrow[d];
        const float* kd = Ks + d * 66 + part;
        #pragma unroll
        for (int j = 0; j < 16; j++) sc[j] += qd * kd[4 * j];
    }
    const float* mrow = mask + ((size_t)b * 64 + qi) * 64;
    float sf[16];
    float mx = -INFINITY;
    #pragma unroll
    for (int j = 0; j < 16; j++) {
        int kj = part + 4 * j;
        float s = sc[j] * 0.0625f + mrow[kj];
        sf[j] = __half2float(__float2half(s));       // -1e9 -> -inf in f16
        mx = fmaxf(mx, sf[j]);
    }
    mx = fmaxf(mx, __shfl_xor_sync(0xffffffffu, mx, 1));
    mx = fmaxf(mx, __shfl_xor_sync(0xffffffffu, mx, 2));
    float sum = 0.f;
    #pragma unroll
    for (int j = 0; j < 16; j++) {
        float dd = __half2float(__float2half(sf[j] - mx));
        float e  = __half2float(__float2half(expf(dd)));
        sf[j] = e; sum += e;
    }
    sum += __shfl_xor_sync(0xffffffffu, sum, 1);
    sum += __shfl_xor_sync(0xffffffffu, sum, 2);
    float* asr = AS + qi * 68;
    float* aout = attn_out ? attn_out + (((size_t)b * HHE + h) * 64 + qi) * 64 : nullptr;
    #pragma unroll
    for (int j = 0; j < 16; j++) {
        int kj = part + 4 * j;
        float a = __half2float(__float2half(sf[j] / sum));
        asr[kj] = a;
        if (aout) aout[kj] = a;
    }
    __syncthreads();

    float acc[64];
    #pragma unroll
    for (int d2 = 0; d2 < 64; d2++) acc[d2] = 0.f;
    for (int kj = 0; kj < 64; kj++) {
        float av = asr[kj];
        const float* vr = Vs + kj * 256 + part;
        #pragma unroll
        for (int d2 = 0; d2 < 64; d2++) acc[d2] += av * vr[4 * d2];
    }
    // fp16 context output (row-major (B,S,H*HD)) for the O-proj GEMM
    __half* aorow = ao + (((size_t)b * 64 + qi) * HHE + h) * HD + part;
    #pragma unroll
    for (int d2 = 0; d2 < 64; d2++) aorow[4 * d2] = __float2half_rn(acc[d2]);
}

// ---------------- launch ----------------
extern "C" void kernel_launch(void* const* d_in, const int* in_sizes, int n_in,
                              void* d_out, int out_size) {
    const float* x      = (const float*)d_in[0];
    const float* mask   = (const float*)d_in[1];
    const int*   pos    = (const int*)  d_in[2];
    const float* invf   = (const float*)d_in[3];
    const float* wq     = (const float*)d_in[4];
    const float* wk     = (const float*)d_in[5];
    const float* wv     = (const float*)d_in[6];
    const float* wo     = (const float*)d_in[7];
    const float* wgate  = (const float*)d_in[8];
    const float* wup    = (const float*)d_in[9];
    const float* wdown  = (const float*)d_in[10];
    const float* ln1    = (const float*)d_in[11];
    const float* ln2    = (const float*)d_in[12];

    float* out = (float*)d_out;
    float* out_h = out;
    const int HID_N = ROWS * DDIM;
    const int ATT_N = BDIM * HHE * SDIM * SDIM;
    float* out_attn = (out_size >= HID_N + ATT_N) ? out + HID_N : nullptr;

    float *q, *k, *v, *gate;
    __half *h1h, *aoh, *mlph, *wqh, *wkh, *wvh, *woh, *wgh, *wuh, *wdh;
    cudaGetSymbolAddress((void**)&q,    g_q);
    cudaGetSymbolAddress((void**)&k,    g_k);
    cudaGetSymbolAddress((void**)&v,    g_v);
    cudaGetSymbolAddress((void**)&gate, g_gate);
    cudaGetSymbolAddress((void**)&h1h,  g_h1h);
    cudaGetSymbolAddress((void**)&aoh,  g_aoh);
    cudaGetSymbolAddress((void**)&mlph, g_mlph);
    cudaGetSymbolAddress((void**)&wqh,  g_wqh);
    cudaGetSymbolAddress((void**)&wkh,  g_wkh);
    cudaGetSymbolAddress((void**)&wvh,  g_wvh);
    cudaGetSymbolAddress((void**)&woh,  g_woh);
    cudaGetSymbolAddress((void**)&wgh,  g_wgh);
    cudaGetSymbolAddress((void**)&wuh,  g_wuh);
    cudaGetSymbolAddress((void**)&wdh,  g_wdh);

    cudaFuncSetAttribute(attn_kernel, cudaFuncAttributeMaxDynamicSharedMemorySize, ATTN_SMEM);
    cudaFuncSetAttribute(gemm_h, cudaFuncAttributeMaxDynamicSharedMemorySize, GEMM_SMEM);

    // 0. convert weights to fp16
    {
        auto cv = [](const float* src, __half* dst, size_t n) {
            int n8 = (int)(n / 8);
            cvt_h_kernel<<<(n8 + 255) / 256, 256>>>((const float4*)src, (half2x4*)dst, n8);
        };
        cv(wq,    wqh, (size_t)DDIM*DDIM);
        cv(wk,    wkh, (size_t)HD*DDIM);
        cv(wv,    wvh, (size_t)HD*DDIM);
        cv(wo,    woh, (size_t)DDIM*DDIM);
        cv(wgate, wgh, (size_t)INTER*DDIM);
        cv(wup,   wuh, (size_t)INTER*DDIM);
        cv(wdown, wdh, (size_t)DDIM*INTER);
    }
    // 1. rmsnorm 1 -> fp16
    rmsnorm_kernel<<<ROWS, 256>>>(x, ln1, (__half2*)h1h);
    // 2. Q projection; K+V fused via blockIdx.z
    gemm_h<<<dim3(ROWS/128, DDIM/256), 256, GEMM_SMEM>>>(h1h, wqh, nullptr, q, nullptr,
                                                         nullptr, nullptr, DDIM, DDIM, 0);
    gemm_h<<<dim3(ROWS/128, 1, 2), 256, GEMM_SMEM>>>(h1h, wkh, wvh, k, v,
                                                     nullptr, nullptr, HD, DDIM, 0);
    // 3. RoPE
    {
        int totq = ROWS * HHE * 128;
        rope_kernel<<<totq / 256, 256>>>(q, pos, invf, HHE, totq);
        int totk = ROWS * 1 * 128;
        rope_kernel<<<totk / 256, 256>>>(k, pos, invf, 1, totk);
    }
    // 4. attention (fp32 probs to out, fp16 context to aoh)
    attn_kernel<<<dim3(HHE, BDIM), 256, ATTN_SMEM>>>(q, k, v, mask, out_attn, aoh);
    // 5. O projection + residual -> out_h
    gemm_h<<<dim3(ROWS/128, DDIM/256), 256, GEMM_SMEM>>>(aoh, woh, nullptr, out_h, nullptr,
                                                         x, nullptr, DDIM, DDIM, 1);
    // 6. rmsnorm 2 -> fp16
    rmsnorm_kernel<<<ROWS, 256>>>(out_h, ln2, (__half2*)h1h);
    // 7. gate GEMM (fp32 out)
    gemm_h<<<dim3(ROWS/128, INTER/256), 256, GEMM_SMEM>>>(h1h, wgh, nullptr, gate, nullptr,
                                                          nullptr, nullptr, INTER, DDIM, 0);
    // 8. up GEMM with fused gelu(gate)*up -> fp16 mlph
    gemm_h<<<dim3(ROWS/128, INTER/256), 256, GEMM_SMEM>>>(h1h, wuh, nullptr, nullptr, nullptr,
                                                          gate, mlph, INTER, DDIM, 2);
    // 9. down projection + residual -> out_h
    gemm_h<<<dim3(ROWS/128, DDIM/256), 256, GEMM_SMEM>>>(mlph, wdh, nullptr, out_h, nullptr,
                                                         out_h, nullptr, DDIM, INTER, 1);
}